// round 11
// baseline (speedup 1.0000x reference)
#include <cuda_runtime.h>
#include <cstdint>

#define B_DIM 2048
#define D_DIM 512
#define H_DIM 2048
#define NS    32

typedef unsigned long long ull;

// ---- scratch ----
__device__ float g_Wt[H_DIM * D_DIM];     // W transposed [2048][512]
__device__ ull   g_cand[NS * B_DIM * 4];  // top-4 keys per slot
__device__ int   g_samp[NS * B_DIM];      // resolved sample index per slot
__device__ float g_temp[NS * B_DIM];      // gaussian temp[i][j]

// ================= tf32 helpers =============================================
__device__ __forceinline__ uint32_t tf32_of(float f) {
    uint32_t u;
    asm("cvt.rna.tf32.f32 %0, %1;" : "=r"(u) : "f"(f));
    return u;
}

#define MMA_TF32(c, A0, A1, A2, A3, B0, B1) \
    asm volatile("mma.sync.aligned.m16n8k8.row.col.f32.tf32.tf32.f32 " \
                 "{%0,%1,%2,%3},{%4,%5,%6,%7},{%8,%9},{%0,%1,%2,%3};" \
                 : "+f"((c)[0]), "+f"((c)[1]), "+f"((c)[2]), "+f"((c)[3]) \
                 : "r"(A0), "r"(A1), "r"(A2), "r"(A3), "r"(B0), "r"(B1))

// ======== h = x @ W : tf32 3-term split, 128x128 tile, K chunks of 16 =======
#define KC 16
#define LDP 136   // padded row stride (floats)
__global__ __launch_bounds__(256) void gemm_mma(const float* __restrict__ x,
                                                const float* __restrict__ W,
                                                float* __restrict__ h) {
    __shared__ uint32_t Ah[KC * LDP], Al[KC * LDP], Bh[KC * LDP], Bl[KC * LDP];
    int tid  = threadIdx.x;
    int bm   = (int)(blockIdx.x >> 4) << 7;
    int bn   = (int)(blockIdx.x & 15) << 7;
    int wid  = tid >> 5, lane = tid & 31;
    int grp  = lane >> 2, tig = lane & 3;
    int moff = (wid >> 2) << 6;   // 0 / 64
    int noff = (wid & 3) << 5;    // 0,32,64,96
    float acc[4][4][4] = {};

    for (int k0 = 0; k0 < D_DIM; k0 += KC) {
        __syncthreads();
#pragma unroll 1
        for (int i = tid; i < 512; i += 256) {
            int row = i >> 2, c0 = (i & 3) << 2;
            float4 v = *(const float4*)(x + (size_t)(bm + row) * D_DIM + k0 + c0);
            float f[4] = {v.x, v.y, v.z, v.w};
#pragma unroll
            for (int j = 0; j < 4; ++j) {
                uint32_t hi = tf32_of(f[j]);
                Ah[(c0 + j) * LDP + row] = hi;
                Al[(c0 + j) * LDP + row] = tf32_of(f[j] - __uint_as_float(hi));
            }
        }
#pragma unroll 1
        for (int i = tid; i < 512; i += 256) {
            int kr = i >> 5, c0 = (i & 31) << 2;
            float4 v = *(const float4*)(W + (size_t)(k0 + kr) * H_DIM + bn + c0);
            float f[4] = {v.x, v.y, v.z, v.w};
#pragma unroll
            for (int j = 0; j < 4; ++j) {
                uint32_t hi = tf32_of(f[j]);
                Bh[kr * LDP + c0 + j] = hi;
                Bl[kr * LDP + c0 + j] = tf32_of(f[j] - __uint_as_float(hi));
            }
        }
        __syncthreads();
#pragma unroll
        for (int ks = 0; ks < KC; ks += 8) {
            uint32_t ah[4][4], al[4][4];
#pragma unroll
            for (int mt = 0; mt < 4; ++mt) {
                int m0 = moff + mt * 16 + grp;
                ah[mt][0] = Ah[(ks + tig) * LDP + m0];
                ah[mt][1] = Ah[(ks + tig) * LDP + m0 + 8];
                ah[mt][2] = Ah[(ks + tig + 4) * LDP + m0];
                ah[mt][3] = Ah[(ks + tig + 4) * LDP + m0 + 8];
                al[mt][0] = Al[(ks + tig) * LDP + m0];
                al[mt][1] = Al[(ks + tig) * LDP + m0 + 8];
                al[mt][2] = Al[(ks + tig + 4) * LDP + m0];
                al[mt][3] = Al[(ks + tig + 4) * LDP + m0 + 8];
            }
#pragma unroll
            for (int nt = 0; nt < 4; ++nt) {
                int n0 = noff + nt * 8 + grp;
                uint32_t b0h = Bh[(ks + tig) * LDP + n0];
                uint32_t b1h = Bh[(ks + tig + 4) * LDP + n0];
                uint32_t b0l = Bl[(ks + tig) * LDP + n0];
                uint32_t b1l = Bl[(ks + tig + 4) * LDP + n0];
#pragma unroll
                for (int mt = 0; mt < 4; ++mt) {
                    MMA_TF32(acc[mt][nt], ah[mt][0], ah[mt][1], ah[mt][2], ah[mt][3], b0h, b1h);
                    MMA_TF32(acc[mt][nt], ah[mt][0], ah[mt][1], ah[mt][2], ah[mt][3], b0l, b1l);
                    MMA_TF32(acc[mt][nt], al[mt][0], al[mt][1], al[mt][2], al[mt][3], b0h, b1h);
                }
            }
        }
    }
#pragma unroll
    for (int mt = 0; mt < 4; ++mt) {
#pragma unroll
        for (int nt = 0; nt < 4; ++nt) {
            int row = bm + moff + mt * 16 + grp;
            int col = bn + noff + nt * 8 + 2 * tig;
            *(float2*)(h + (size_t)row * H_DIM + col) =
                make_float2(acc[mt][nt][0], acc[mt][nt][1]);
            *(float2*)(h + (size_t)(row + 8) * H_DIM + col) =
                make_float2(acc[mt][nt][2], acc[mt][nt][3]);
        }
    }
}

// ====== threefry2x32 partitionable, 2 chains, adds forced onto IMAD (fma) ===
// MADD: dst += src via mad.lo.u32 with runtime-opaque multiplier `one`
#define MADD(dst, src) asm("mad.lo.u32 %0, %1, %2, %0;" : "+r"(dst) : "r"(src), "r"(one))

__device__ __forceinline__ void draw_bits2(uint32_t La, uint32_t Lb, uint32_t one,
                                           uint32_t& oa, uint32_t& ob) {
    const uint32_t ks1   = 42u;
    const uint32_t ks2   = 0x1BD11BDAu ^ 42u;
    uint32_t a0 = 0u, a1 = La;  MADD(a1, ks1);
    uint32_t b0 = 0u, b1 = Lb;  MADD(b1, ks1);
#define TFR2(r) { MADD(a0, a1); MADD(b0, b1); \
                  a1 = __funnelshift_l(a1, a1, (r)); b1 = __funnelshift_l(b1, b1, (r)); \
                  a1 ^= a0; b1 ^= b0; }
    TFR2(13) TFR2(15) TFR2(26) TFR2(6)
    MADD(a0, ks1); MADD(a1, ks2 + 1u);   MADD(b0, ks1); MADD(b1, ks2 + 1u);
    TFR2(17) TFR2(29) TFR2(16) TFR2(24)
    MADD(a0, ks2); MADD(a1, 2u);         MADD(b0, ks2); MADD(b1, 2u);
    TFR2(13) TFR2(15) TFR2(26) TFR2(6)
    MADD(a1, ks1 + 3u);                  MADD(b1, ks1 + 3u);
    TFR2(17) TFR2(29) TFR2(16) TFR2(24)
    MADD(a0, ks1); MADD(a1, ks2 + 4u);   MADD(b0, ks1); MADD(b1, ks2 + 4u);
    TFR2(13) TFR2(15) TFR2(26) TFR2(6)
    MADD(a0, ks2); MADD(a1, 5u);         MADD(b0, ks2); MADD(b1, 5u);
#undef TFR2
    oa = a0 ^ a1;
    ob = b0 ^ b1;
}

__device__ __forceinline__ void ins4(ull t[4], ull k) {
    if (k <= t[3]) return;
    if (k > t[0])      { t[3] = t[2]; t[2] = t[1]; t[1] = t[0]; t[0] = k; }
    else if (k > t[1]) { t[3] = t[2]; t[2] = t[1]; t[1] = k; }
    else if (k > t[2]) { t[3] = t[2]; t[2] = k; }
    else               { t[3] = k; }
}

// ======= MEGA: 12288 blocks, l=bid%12: 0-7 track, 8 transpose, 9 softmax(x2),
//         10-11 zero (grid-stride) ============================================
__global__ __launch_bounds__(256, 6) void mega_kernel(const float* __restrict__ h,
                                                      const float* __restrict__ W,
                                                      float* __restrict__ z,
                                                      float* __restrict__ oh) {
    __shared__ float sm[1088];
    int bid = blockIdx.x;
    int l = bid % 12;
    int g = bid / 12;        // 0..1023
    int tid = threadIdx.x;
    uint32_t one = blockDim.x >> 8;   // ==1, opaque to the compiler

    if (l < 8) {
        // ---------------- track: one warp per slot, 2-way ILP ----------------
        int w    = (g * 8 + l) * 8 + (tid >> 5);
        int lane = tid & 31;
        ull t[4] = {0, 0, 0, 0};
        uint32_t L    = ((uint32_t)w << 11) + (uint32_t)lane;
        uint32_t idxk = 2047u - (uint32_t)lane;
#pragma unroll 2
        for (int it = 0; it < 32; ++it) {
            uint32_t oa, ob;
            draw_bits2(L, L + 32u, one, oa, ob);
            ins4(t, ((ull)oa << 32) | (ull)idxk);
            ins4(t, ((ull)ob << 32) | (ull)(idxk - 32u));
            L += 64u; idxk -= 64u;
        }
#pragma unroll
        for (int s = 0; s < 4; ++s) {
            ull mine = t[0];
            ull m = mine;
#pragma unroll
            for (int off = 16; off; off >>= 1) {
                ull o = __shfl_down_sync(0xffffffffu, m, off);
                if (o > m) m = o;
            }
            m = __shfl_sync(0xffffffffu, m, 0);
            if (mine == m && m != 0ull) { t[0] = t[1]; t[1] = t[2]; t[2] = t[3]; t[3] = 0ull; }
            if (lane == 0) g_cand[(size_t)w * 4 + s] = m;
        }
    } else if (l == 8) {
        // ---------------- transpose W -> Wt ----------------
        int bx = (g & 63) << 5;   // H
        int by = (g >> 6) << 5;   // D
        int tx = tid & 31, ty = tid >> 5;  // ty 0..7
#pragma unroll
        for (int k = 0; k < 32; k += 8)
            sm[(ty + k) * 33 + tx] = W[(size_t)(by + ty + k) * H_DIM + bx + tx];
        __syncthreads();
#pragma unroll
        for (int k = 0; k < 32; k += 8)
            g_Wt[(size_t)(bx + ty + k) * D_DIM + by + tx] = sm[tx * 33 + ty + k];
    } else if (l == 9) {
        // ---------------- softmax: rows 2g, 2g+1 ----------------
#pragma unroll 1
        for (int r = 0; r < 2; ++r) {
            int b = g * 2 + r;
            const float* row = h + (size_t)b * H_DIM;
            float v[8];
            float mx = -3.4e38f;
#pragma unroll
            for (int k = 0; k < 8; ++k) { v[k] = row[tid + (k << 8)]; mx = fmaxf(mx, v[k]); }
            sm[tid] = mx; __syncthreads();
            for (int s = 128; s; s >>= 1) { if (tid < s) sm[tid] = fmaxf(sm[tid], sm[tid + s]); __syncthreads(); }
            mx = sm[0]; __syncthreads();
            float sum = 0.f;
#pragma unroll
            for (int k = 0; k < 8; ++k) { v[k] = expf(v[k] - mx); sum += v[k]; }
            sm[tid] = sum; __syncthreads();
            for (int s = 128; s; s >>= 1) { if (tid < s) sm[tid] += sm[tid + s]; __syncthreads(); }
            sum = sm[0]; __syncthreads();
            float* zr = z + (size_t)b * H_DIM;
#pragma unroll
            for (int k = 0; k < 8; ++k) zr[tid + (k << 8)] = v[k] / sum;
        }
    } else {
        // ---------------- zero onehot (grid-stride float4) ----------------
        int zid = (l - 10) * 1024 + g;              // 0..2047
        float4* p = (float4*)oh;
        float4 zf = make_float4(0.f, 0.f, 0.f, 0.f);
        for (int i = zid * 256 + tid; i < 33554432; i += 2048 * 256) p[i] = zf;
    }
}

// ================= resolve: exact-score 4 candidates per slot ================
__global__ __launch_bounds__(256) void resolve_kernel(const float* __restrict__ z) {
    int w = blockIdx.x * 256 + threadIdx.x;
    int b = w & 2047;
    float best = -3.4e38f;
    uint32_t bidx = 0xffffffffu;
#pragma unroll
    for (int s = 0; s < 4; ++s) {
        ull key = g_cand[(size_t)w * 4 + s];
        if (key == 0ull) continue;
        uint32_t o   = (uint32_t)(key >> 32);
        uint32_t idx = 2047u - (uint32_t)(key & 2047u);
        float f = __uint_as_float((o >> 9) | 0x3f800000u) - 1.0f;
        float u = fmaxf(f, 1.17549435e-38f);
        float sc = -logf(-logf(u)) + z[(size_t)b * H_DIM + idx];
        if (sc > best || (sc == best && idx < bidx)) { best = sc; bidx = idx; }
    }
    g_samp[w] = (int)bidx;
}

// ========== decode gather + gaussian temp + fused one-hot scatter ============
__global__ __launch_bounds__(256) void decode_kernel(const float* __restrict__ x,
                                                     float* __restrict__ xdec,
                                                     float* __restrict__ oh) {
    int w    = blockIdx.x * 8 + (threadIdx.x >> 5);
    int lane = threadIdx.x & 31;
    int i = w >> 11, j = w & 2047;
    int s = g_samp[((j & 31) << 11) | ((i << 6) + (j >> 5))];
    const float4* wr = (const float4*)(g_Wt + (size_t)s * D_DIM);
    const float4* xr = (const float4*)(x + (size_t)j * D_DIM);
    float4* od = (float4*)(xdec + (size_t)w * D_DIM);
    float ssd = 0.f;
#pragma unroll
    for (int tt = 0; tt < 4; ++tt) {
        int idx = lane + (tt << 5);
        float4 a = xr[idx], c = wr[idx];
        od[idx] = c;
        float dx = a.x - c.x, dy = a.y - c.y, dz = a.z - c.z, dw = a.w - c.w;
        ssd += dx * dx + dy * dy + dz * dz + dw * dw;
    }
#pragma unroll
    for (int off = 16; off; off >>= 1) ssd += __shfl_xor_sync(0xffffffffu, ssd, off);
    if (lane == 0) {
        g_temp[w] = 0.3989422804014327f * expf(-0.5f * ssd);
        oh[((size_t)w << 11) + (size_t)s] = 1.0f;
    }
}

// ================= weight ====================================================
__global__ void weight_kernel(float* __restrict__ wout) {
    int j = blockIdx.x * 256 + threadIdx.x;
    float tv[NS];
    float sum = 0.f;
#pragma unroll
    for (int i = 0; i < NS; ++i) { tv[i] = g_temp[(size_t)i * B_DIM + j]; sum += tv[i]; }
    float mean = sum * (1.0f / 32.0f);
#pragma unroll
    for (int i = 0; i < NS; ++i) wout[(size_t)i * B_DIM + j] = tv[i] / mean;
}

// ================= launch ====================================================
extern "C" void kernel_launch(void* const* d_in, const int* in_sizes, int n_in,
                              void* d_out, int out_size) {
    const float* x = (const float*)d_in[0];
    const float* W = (const float*)d_in[1];
    float* out = (float*)d_out;

    float* h    = out;
    float* z    = out + (size_t)4194304;
    float* oh   = out + (size_t)8388608;
    float* xdec = out + (size_t)142606336;
    float* wt   = out + (size_t)176160768;

    gemm_mma<<<256, 256>>>(x, W, h);
    mega_kernel<<<12288, 256>>>(h, W, z, oh);
    resolve_kernel<<<256, 256>>>(z);
    decode_kernel<<<8192, 256>>>(x, xdec, oh);
    weight_kernel<<<8, 256>>>(wt);
}

// round 12
// speedup vs baseline: 1.1113x; 1.1113x over previous
#include <cuda_runtime.h>
#include <cstdint>

#define B_DIM 2048
#define D_DIM 512
#define H_DIM 2048
#define NS    32

typedef unsigned long long ull;

// ---- scratch ----
__device__ float g_Wt[H_DIM * D_DIM];     // W transposed [2048][512]
__device__ float g_temp[NS * B_DIM];      // gaussian temp[i][j]

// ================= tf32 helpers =============================================
__device__ __forceinline__ uint32_t tf32_of(float f) {
    uint32_t u;
    asm("cvt.rna.tf32.f32 %0, %1;" : "=r"(u) : "f"(f));
    return u;
}

#define MMA_TF32(c, A0, A1, A2, A3, B0, B1) \
    asm volatile("mma.sync.aligned.m16n8k8.row.col.f32.tf32.tf32.f32 " \
                 "{%0,%1,%2,%3},{%4,%5,%6,%7},{%8,%9},{%0,%1,%2,%3};" \
                 : "+f"((c)[0]), "+f"((c)[1]), "+f"((c)[2]), "+f"((c)[3]) \
                 : "r"(A0), "r"(A1), "r"(A2), "r"(A3), "r"(B0), "r"(B1))

// == prefix: h = x @ W (tf32 3-term, 128x128 tiles, bid<256) + transpose rider
#define KC 16
#define LDP 136
__global__ __launch_bounds__(256) void gemm_mma(const float* __restrict__ x,
                                                const float* __restrict__ W,
                                                float* __restrict__ h) {
    __shared__ uint32_t Ah[KC * LDP], Al[KC * LDP], Bh[KC * LDP], Bl[KC * LDP];
    int tid = threadIdx.x;
    int bid = blockIdx.x;
    if (bid >= 256) {
        // ---- transpose W -> Wt : 4 tiles of 32x32 per block ----
        float* sm = (float*)Ah;   // 32*33 floats
        int g2 = bid - 256;
        int tx = tid & 31, ty = tid >> 5;  // ty 0..7
        for (int tt = 0; tt < 4; ++tt) {
            int tile = g2 * 4 + tt;
            int bx = (tile & 63) << 5;   // H
            int by = (tile >> 6) << 5;   // D
            __syncthreads();
#pragma unroll
            for (int k = 0; k < 32; k += 8)
                sm[(ty + k) * 33 + tx] = W[(size_t)(by + ty + k) * H_DIM + bx + tx];
            __syncthreads();
#pragma unroll
            for (int k = 0; k < 32; k += 8)
                g_Wt[(size_t)(bx + ty + k) * D_DIM + by + tx] = sm[tx * 33 + ty + k];
        }
        return;
    }
    int bm   = (bid >> 4) << 7;
    int bn   = (bid & 15) << 7;
    int wid  = tid >> 5, lane = tid & 31;
    int grp  = lane >> 2, tig = lane & 3;
    int moff = (wid >> 2) << 6;
    int noff = (wid & 3) << 5;
    float acc[4][4][4] = {};

    for (int k0 = 0; k0 < D_DIM; k0 += KC) {
        __syncthreads();
#pragma unroll 1
        for (int i = tid; i < 512; i += 256) {
            int row = i >> 2, c0 = (i & 3) << 2;
            float4 v = *(const float4*)(x + (size_t)(bm + row) * D_DIM + k0 + c0);
            float f[4] = {v.x, v.y, v.z, v.w};
#pragma unroll
            for (int j = 0; j < 4; ++j) {
                uint32_t hi = tf32_of(f[j]);
                Ah[(c0 + j) * LDP + row] = hi;
                Al[(c0 + j) * LDP + row] = tf32_of(f[j] - __uint_as_float(hi));
            }
        }
#pragma unroll 1
        for (int i = tid; i < 512; i += 256) {
            int kr = i >> 5, c0 = (i & 31) << 2;
            float4 v = *(const float4*)(W + (size_t)(k0 + kr) * H_DIM + bn + c0);
            float f[4] = {v.x, v.y, v.z, v.w};
#pragma unroll
            for (int j = 0; j < 4; ++j) {
                uint32_t hi = tf32_of(f[j]);
                Bh[kr * LDP + c0 + j] = hi;
                Bl[kr * LDP + c0 + j] = tf32_of(f[j] - __uint_as_float(hi));
            }
        }
        __syncthreads();
#pragma unroll
        for (int ks = 0; ks < KC; ks += 8) {
            uint32_t ah[4][4], al[4][4];
#pragma unroll
            for (int mt = 0; mt < 4; ++mt) {
                int m0 = moff + mt * 16 + grp;
                ah[mt][0] = Ah[(ks + tig) * LDP + m0];
                ah[mt][1] = Ah[(ks + tig) * LDP + m0 + 8];
                ah[mt][2] = Ah[(ks + tig + 4) * LDP + m0];
                ah[mt][3] = Ah[(ks + tig + 4) * LDP + m0 + 8];
                al[mt][0] = Al[(ks + tig) * LDP + m0];
                al[mt][1] = Al[(ks + tig) * LDP + m0 + 8];
                al[mt][2] = Al[(ks + tig + 4) * LDP + m0];
                al[mt][3] = Al[(ks + tig + 4) * LDP + m0 + 8];
            }
#pragma unroll
            for (int nt = 0; nt < 4; ++nt) {
                int n0 = noff + nt * 8 + grp;
                uint32_t b0h = Bh[(ks + tig) * LDP + n0];
                uint32_t b1h = Bh[(ks + tig + 4) * LDP + n0];
                uint32_t b0l = Bl[(ks + tig) * LDP + n0];
                uint32_t b1l = Bl[(ks + tig + 4) * LDP + n0];
#pragma unroll
                for (int mt = 0; mt < 4; ++mt) {
                    MMA_TF32(acc[mt][nt], ah[mt][0], ah[mt][1], ah[mt][2], ah[mt][3], b0h, b1h);
                    MMA_TF32(acc[mt][nt], ah[mt][0], ah[mt][1], ah[mt][2], ah[mt][3], b0l, b1l);
                    MMA_TF32(acc[mt][nt], al[mt][0], al[mt][1], al[mt][2], al[mt][3], b0h, b1h);
                }
            }
        }
    }
#pragma unroll
    for (int mt = 0; mt < 4; ++mt) {
#pragma unroll
        for (int nt = 0; nt < 4; ++nt) {
            int row = bm + moff + mt * 16 + grp;
            int col = bn + noff + nt * 8 + 2 * tig;
            *(float2*)(h + (size_t)row * H_DIM + col) =
                make_float2(acc[mt][nt][0], acc[mt][nt][1]);
            *(float2*)(h + (size_t)(row + 8) * H_DIM + col) =
                make_float2(acc[mt][nt][2], acc[mt][nt][3]);
        }
    }
}

// ================= softmax ===================================================
__global__ __launch_bounds__(256) void softmax_kernel(const float* __restrict__ h,
                                                      float* __restrict__ z) {
    int b = blockIdx.x;
    int t = threadIdx.x;
    const float* row = h + (size_t)b * H_DIM;
    float v[8];
    float mx = -3.4e38f;
#pragma unroll
    for (int k = 0; k < 8; ++k) { v[k] = row[t + (k << 8)]; mx = fmaxf(mx, v[k]); }
    __shared__ float red[256];
    red[t] = mx; __syncthreads();
    for (int s = 128; s; s >>= 1) { if (t < s) red[t] = fmaxf(red[t], red[t + s]); __syncthreads(); }
    mx = red[0]; __syncthreads();
    float sum = 0.f;
#pragma unroll
    for (int k = 0; k < 8; ++k) { v[k] = expf(v[k] - mx); sum += v[k]; }
    red[t] = sum; __syncthreads();
    for (int s = 128; s; s >>= 1) { if (t < s) red[t] += red[t + s]; __syncthreads(); }
    sum = red[0];
    float* zr = z + (size_t)b * H_DIM;
#pragma unroll
    for (int k = 0; k < 8; ++k) zr[t + (k << 8)] = v[k] / sum;
}

// ====== JAX threefry2x32 partitionable, TWO chains interleaved (ILP=2) ======
__device__ __forceinline__ void draw_bits2(uint32_t La, uint32_t Lb,
                                           uint32_t& oa, uint32_t& ob) {
    const uint32_t ks1 = 42u;
    const uint32_t ks2 = 0x1BD11BDAu ^ 42u;
    uint32_t a0 = 0u, a1 = La + ks1;
    uint32_t b0 = 0u, b1 = Lb + ks1;
#define TFR2(r) { a0 += a1; b0 += b1; \
                  a1 = __funnelshift_l(a1, a1, (r)); b1 = __funnelshift_l(b1, b1, (r)); \
                  a1 ^= a0; b1 ^= b0; }
    TFR2(13) TFR2(15) TFR2(26) TFR2(6)
    a0 += ks1; a1 += ks2 + 1u;   b0 += ks1; b1 += ks2 + 1u;
    TFR2(17) TFR2(29) TFR2(16) TFR2(24)
    a0 += ks2; a1 += 2u;         b0 += ks2; b1 += 2u;
    TFR2(13) TFR2(15) TFR2(26) TFR2(6)
    a1 += ks1 + 3u;              b1 += ks1 + 3u;
    TFR2(17) TFR2(29) TFR2(16) TFR2(24)
    a0 += ks1; a1 += ks2 + 4u;   b0 += ks1; b1 += ks2 + 4u;
    TFR2(13) TFR2(15) TFR2(26) TFR2(6)
    a0 += ks2; a1 += 5u;         b0 += ks2; b1 += 5u;
#undef TFR2
    oa = a0 ^ a1;
    ob = b0 ^ b1;
}

__device__ __forceinline__ void ins4(ull t[4], ull k) {
    if (k <= t[3]) return;
    if (k > t[0])      { t[3] = t[2]; t[2] = t[1]; t[1] = t[0]; t[0] = k; }
    else if (k > t[1]) { t[3] = t[2]; t[2] = t[1]; t[1] = k; }
    else if (k > t[2]) { t[3] = t[2]; t[2] = k; }
    else               { t[3] = k; }
}

// ======= MEGA: one warp = one slot v: track -> resolve -> decode -> onehot row
__global__ __launch_bounds__(256, 4) void mega_kernel(const float* __restrict__ x,
                                                      const float* __restrict__ z,
                                                      float* __restrict__ oh,
                                                      float* __restrict__ xdec) {
    int v    = blockIdx.x * 8 + (threadIdx.x >> 5);   // 0..65535 = n*2048 + b
    int lane = threadIdx.x & 31;
    int b = v & 2047;
    int n = v >> 11;

    // ---- track: top-4 gumbel-key candidates over 2048 draws ----
    ull t[4] = {0, 0, 0, 0};
    uint32_t L    = ((uint32_t)v << 11) + (uint32_t)lane;
    uint32_t idxk = 2047u - (uint32_t)lane;
#pragma unroll 2
    for (int it = 0; it < 32; ++it) {
        uint32_t oa, ob;
        draw_bits2(L, L + 32u, oa, ob);
        ins4(t, ((ull)oa << 32) | (ull)idxk);
        ins4(t, ((ull)ob << 32) | (ull)(idxk - 32u));
        L += 64u; idxk -= 64u;
    }
    // ---- merge per-lane top4 -> warp top4 (lanes 0-3 hold them) ----
    ull mykey = 0ull;
#pragma unroll
    for (int s = 0; s < 4; ++s) {
        ull mine = t[0];
        ull m = mine;
#pragma unroll
        for (int off = 16; off; off >>= 1) {
            ull o = __shfl_down_sync(0xffffffffu, m, off);
            if (o > m) m = o;
        }
        m = __shfl_sync(0xffffffffu, m, 0);
        if (mine == m && m != 0ull) { t[0] = t[1]; t[1] = t[2]; t[2] = t[3]; t[3] = 0ull; }
        if (lane == s) mykey = m;
    }
    // ---- resolve: exact-score candidates, argmax w/ idx tie-break ----
    float sc = -3.4e38f;
    uint32_t hidx = 0xffffffffu;
    if (lane < 4 && mykey != 0ull) {
        uint32_t o = (uint32_t)(mykey >> 32);
        hidx = 2047u - (uint32_t)(mykey & 2047u);
        float f = __uint_as_float((o >> 9) | 0x3f800000u) - 1.0f;
        float u = fmaxf(f, 1.17549435e-38f);
        float g = -logf(-logf(u));
        sc = g + z[(size_t)b * H_DIM + hidx];
    }
#pragma unroll
    for (int off = 1; off < 4; off <<= 1) {
        float    so = __shfl_xor_sync(0xffffffffu, sc, off);
        uint32_t ho = __shfl_xor_sync(0xffffffffu, hidx, off);
        if (so > sc || (so == sc && ho < hidx)) { sc = so; hidx = ho; }
    }
    int s = (int)__shfl_sync(0xffffffffu, hidx, 0);

    // ---- decode output slot w = sigma^-1(v) ----
    int i = b >> 6;
    int j = ((b & 63) << 5) + n;
    int w = (i << 11) + j;

    const float4* wr = (const float4*)(g_Wt + (size_t)s * D_DIM);
    const float4* xr = (const float4*)(x + (size_t)j * D_DIM);
    float4* od = (float4*)(xdec + (size_t)w * D_DIM);
    float ssd = 0.f;
#pragma unroll
    for (int tt = 0; tt < 4; ++tt) {
        int idx = lane + (tt << 5);
        float4 a = xr[idx], c = wr[idx];
        od[idx] = c;
        float dx = a.x - c.x, dy = a.y - c.y, dz = a.z - c.z, dw = a.w - c.w;
        ssd += dx * dx + dy * dy + dz * dz + dw * dw;
    }
    // ---- one-hot row: whole row authored by this warp (no pre-zero) ----
    float4* ohp = (float4*)(oh + ((size_t)w << 11));
    float4 zf = make_float4(0.f, 0.f, 0.f, 0.f);
#pragma unroll
    for (int q = 0; q < 16; ++q) ohp[(q << 5) + lane] = zf;
    if (((s >> 2) & 31) == lane)
        oh[((size_t)w << 11) + (size_t)s] = 1.0f;   // same-thread ordering

#pragma unroll
    for (int off = 16; off; off >>= 1) ssd += __shfl_xor_sync(0xffffffffu, ssd, off);
    if (lane == 0) g_temp[w] = 0.3989422804014327f * expf(-0.5f * ssd);
}

// ================= weight ====================================================
__global__ void weight_kernel(float* __restrict__ wout) {
    int j = blockIdx.x * 256 + threadIdx.x;
    float tv[NS];
    float sum = 0.f;
#pragma unroll
    for (int i = 0; i < NS; ++i) { tv[i] = g_temp[(size_t)i * B_DIM + j]; sum += tv[i]; }
    float mean = sum * (1.0f / 32.0f);
#pragma unroll
    for (int i = 0; i < NS; ++i) wout[(size_t)i * B_DIM + j] = tv[i] / mean;
}

// ================= launch ====================================================
extern "C" void kernel_launch(void* const* d_in, const int* in_sizes, int n_in,
                              void* d_out, int out_size) {
    const float* x = (const float*)d_in[0];
    const float* W = (const float*)d_in[1];
    float* out = (float*)d_out;

    float* h    = out;
    float* z    = out + (size_t)4194304;
    float* oh   = out + (size_t)8388608;
    float* xdec = out + (size_t)142606336;
    float* wt   = out + (size_t)176160768;

    gemm_mma<<<512, 256>>>(x, W, h);       // 256 gemm + 256 transpose blocks
    softmax_kernel<<<2048, 256>>>(h, z);
    mega_kernel<<<8192, 256>>>(x, z, oh, xdec);
    weight_kernel<<<8, 256>>>(wt);
}